// round 13
// baseline (speedup 1.0000x reference)
#include <cuda_runtime.h>
#include <cuda_fp16.h>
#include <mma.h>
#include <cstdint>
using namespace nvcuda;

// ---------------- problem constants ----------------
#define BB    16
#define TT    3000
#define CC    32
#define HH    32
#define WW    375
#define DSW   192
#define PP    32
#define DMODEL 512
#define HID   128
#define NF    128

#define ACOUSTIC_SIZE (BB * NF * 64 * DMODEL)
#define ALPHA_OFF     ACOUSTIC_SIZE
#define QTY_OFF       (ALPHA_OFF + BB * TT)

#define NROWS   (BB * NF * 32)     // 65536 GEMM rows
#define KS_SW   13                 // swin k-steps of 16 (12 data + bias step)
#define KS_PI   3                  // pitch k-steps of 16
#define NTILES  4                  // DMODEL / 128

// ---------------- scratch ----------------
__device__ int    g_fire_w[BB * NF];
__device__ float  g_qdiff[BB];
__device__ __align__(256) __half g_Api[(size_t)KS_PI * NROWS * 16];
__device__ __align__(256) __half g_Bsw[NTILES * KS_SW * 2048];
__device__ __align__(256) __half g_Bpi[NTILES * KS_PI * 2048];

// ---------------- helpers ----------------
__device__ __forceinline__ float warp_sum(float v) {
#pragma unroll
    for (int o = 16; o > 0; o >>= 1) v += __shfl_xor_sync(0xffffffffu, v, o);
    return v;
}
__device__ __forceinline__ void cp16s(unsigned saddr, const void* g) {
    asm volatile("cp.async.cg.shared.global [%0], [%1], 16;" :: "r"(saddr), "l"(g));
}
__device__ __forceinline__ void cp_commit() {
    asm volatile("cp.async.commit_group;" ::: "memory");
}
template <int N>
__device__ __forceinline__ void cp_wait() {
    asm volatile("cp.async.wait_group %0;" :: "n"(N) : "memory");
}

// ============================================================
// Kernel 1: alpha — 8 consecutive t per warp, float4 weight LDS
// ============================================================
__global__ __launch_bounds__(256) void alpha_kernel(
    const float* __restrict__ fs,
    const float* __restrict__ conv_w,
    const float* __restrict__ ln_w,  const float* __restrict__ ln_b,
    const float* __restrict__ dense_w, const float* __restrict__ dense_b,
    const float* __restrict__ proj_w,  const float* __restrict__ proj_b,
    float* __restrict__ alpha_out)
{
    __shared__ float4 s_dw4[CC * 32];
    __shared__ float4 s_db4[32], s_pw4[32];
    __shared__ float  s_cw[CC * 3], s_lnw[CC], s_lnb[CC];

    int tid = threadIdx.x;
    for (int i = tid; i < CC * HID; i += 256) {
        int cc = i >> 7, j = i & 127;
        int q = j >> 5, l = j & 31;
        ((float*)s_dw4)[cc * 128 + l * 4 + q] = dense_w[i];
    }
    if (tid < HID) {
        int q = tid >> 5, l = tid & 31;
        ((float*)s_db4)[l * 4 + q] = dense_b[tid];
        ((float*)s_pw4)[l * 4 + q] = proj_w[tid];
    }
    if (tid < CC * 3) s_cw[tid] = conv_w[tid];
    if (tid < CC) { s_lnw[tid] = ln_w[tid]; s_lnb[tid] = ln_b[tid]; }
    __syncthreads();

    int warp = tid >> 5, lane = tid & 31;
    int g = blockIdx.x * 8 + warp;
    int t0 = (g * 8) % TT;
    int b  = (g * 8) / TT;

    const float* base = fs + ((size_t)b * TT + t0) * CC + lane;
    float xv[10];
#pragma unroll
    for (int j = 0; j < 10; j++) {
        int t = t0 - 1 + j;
        xv[j] = (t >= 0 && t < TT) ? base[(j - 1) * CC] : 0.f;
    }

    float cw0 = s_cw[lane * 3], cw1 = s_cw[lane * 3 + 1], cw2 = s_cw[lane * 3 + 2];
    float lnw = s_lnw[lane], lnb = s_lnb[lane];

    float xn[8];
#pragma unroll
    for (int i = 0; i < 8; i++) {
        float x = fmaf(cw0, xv[i], fmaf(cw1, xv[i + 1], cw2 * xv[i + 2])) + xv[i + 1];
        float mu  = warp_sum(x) * (1.f / CC);
        float d   = x - mu;
        float var = warp_sum(d * d) * (1.f / CC);
        xn[i] = d * rsqrtf(var + 1e-5f) * lnw + lnb;
    }

    float4 db = s_db4[lane];
    float4 h[8] = {db, db, db, db, db, db, db, db};
#pragma unroll
    for (int cc = 0; cc < CC; cc++) {
        float4 w = s_dw4[cc * 32 + lane];
#pragma unroll
        for (int i = 0; i < 8; i++) {
            float v = __shfl_sync(0xffffffffu, xn[i], cc);
            h[i].x = fmaf(v, w.x, h[i].x);
            h[i].y = fmaf(v, w.y, h[i].y);
            h[i].z = fmaf(v, w.z, h[i].z);
            h[i].w = fmaf(v, w.w, h[i].w);
        }
    }

    float4 pw = s_pw4[lane];
    float ps[8];
#pragma unroll
    for (int i = 0; i < 8; i++) {
        float p = fmaxf(h[i].x, 0.f) * pw.x + fmaxf(h[i].y, 0.f) * pw.y
                + fmaxf(h[i].z, 0.f) * pw.z + fmaxf(h[i].w, 0.f) * pw.w;
        ps[i] = warp_sum(p);
    }

    if (lane < 8) {
        float psel = ps[0];
#pragma unroll
        for (int i = 1; i < 8; i++) if (lane == i) psel = ps[i];
        float a  = psel + proj_b[0];
        float sp = fmaxf(a, 0.f) + log1pf(expf(-fabsf(a)));
        alpha_out[(size_t)b * TT + t0 + lane] = sp;
    }
}

// ============================================================
// Kernel 2: fires (warp-scan, 2 barriers)
// ============================================================
__global__ __launch_bounds__(1024) void fires_kernel(
    const float* __restrict__ alpha, const int* __restrict__ tlen)
{
    __shared__ int   s_wsum[32];
    __shared__ int   s_frame[NF];
    __shared__ float s_red[32];

    int b = blockIdx.x, tid = threadIdx.x;
    int lane = tid & 31, warp = tid >> 5;
    if (tid < NF) s_frame[tid] = TT - 1;

    const float* arow = alpha + (size_t)b * TT;
    int base = tid * 3;
    int pred[3] = {0, 0, 0};
    int mycnt = 0; float onset = 0.f;
#pragma unroll
    for (int i = 0; i < 3; i++) {
        int t = base + i;
        if (t < TT) {
            float a = arow[t];
            int pr = (a > 1.0f);
            pred[i] = pr; mycnt += pr;
            onset += 1.f / (1.f + expf(-(a - 1.0f) * 10.f));
        }
    }
    int scan = mycnt;
#pragma unroll
    for (int o = 1; o < 32; o <<= 1) {
        int v = __shfl_up_sync(0xffffffffu, scan, o);
        if (lane >= o) scan += v;
    }
    if (lane == 31) s_wsum[warp] = scan;
    float os = warp_sum(onset);
    if (lane == 0) s_red[warp] = os;
    __syncthreads();
    if (warp == 0) {
        int ws = s_wsum[lane];
#pragma unroll
        for (int o = 1; o < 32; o <<= 1) {
            int v = __shfl_up_sync(0xffffffffu, ws, o);
            if (lane >= o) ws += v;
        }
        s_wsum[lane] = ws;
        float v = warp_sum(s_red[lane]);
        if (lane == 0) g_qdiff[b] = fabsf(v - (float)tlen[b]);
    }
    __syncthreads();
    int c = scan - mycnt + (warp > 0 ? s_wsum[warp - 1] : 0);
#pragma unroll
    for (int i = 0; i < 3; i++) {
        if (pred[i]) {
            c += 1;
            if (c <= NF) s_frame[c - 1] = base + i;
        }
    }
    __syncthreads();
    if (tid < NF) g_fire_w[b * NF + tid] = s_frame[tid] >> 3;
}

__global__ void qty_kernel(float* __restrict__ out) {
    int tid = threadIdx.x;
    float v = (tid < BB) ? g_qdiff[tid] : 0.f;
    v = warp_sum(v);
    if (tid == 0) out[0] = v * (1.f / BB);
}

// ============================================================
// Packing kernels (B for both GEMMs + pitch A)
// ============================================================
__global__ __launch_bounds__(256) void pack_b_kernel(
    const float* __restrict__ sw_w, const float* __restrict__ sw_b,
    const float* __restrict__ pi_w, const float* __restrict__ pi_b)
{
    int idx = blockIdx.x * 256 + threadIdx.x;
    const int SWTOT = NTILES * KS_SW * 2048;
    if (idx < SWTOT) {
        int nt = idx / (KS_SW * 2048);
        int rem = idx % (KS_SW * 2048);
        int j = rem / 2048, e = rem % 2048;
        int kr = e >> 7, n = e & 127;
        int k = j * 16 + kr;
        float v = (k < DSW) ? sw_w[k * DMODEL + nt * 128 + n]
                : (k == DSW ? sw_b[nt * 128 + n] : 0.f);
        g_Bsw[idx] = __float2half_rn(v);
    } else {
        int x = idx - SWTOT;
        if (x >= NTILES * KS_PI * 2048) return;
        int nt = x / (KS_PI * 2048);
        int rem = x % (KS_PI * 2048);
        int j = rem / 2048, e = rem % 2048;
        int kr = e >> 7, n = e & 127;
        int k = j * 16 + kr;
        float v = (k < 32) ? pi_w[k * DMODEL + nt * 128 + n]
                : (k == 32 ? pi_b[nt * 128 + n] : 0.f);
        g_Bpi[x] = __float2half_rn(v);
    }
}

__global__ __launch_bounds__(256) void pack_a_pitch(const float* __restrict__ pitch)
{
    int warp = threadIdx.x >> 5, lane = threadIdx.x & 31;
    int r = blockIdx.x * 8 + warp;
    float v = pitch[(size_t)r * 32 + lane];
    g_Api[((size_t)(lane >> 4) * NROWS + r) * 16 + (lane & 15)] = __float2half_rn(v);
    if (lane < 16)
        g_Api[((size_t)2 * NROWS + r) * 16 + lane] =
            __float2half_rn(lane == 0 ? 1.f : 0.f);
}

// ============================================================
// pitch GEMM: R10-proven static-smem 3-stage fp16 wmma
// ============================================================
#define ASTR 24
#define BSTR 136

__global__ __launch_bounds__(256, 2) void pitch_gemm(float* __restrict__ out)
{
    const int NSTAGE = 3, KSTEPS = KS_PI;
    __shared__ __align__(16) __half As[NSTAGE][128 * ASTR];
    __shared__ __align__(16) __half Bs[NSTAGE][16 * BSTR];

    int tid = threadIdx.x;
    int m0 = blockIdx.y * 128;
    int nt = blockIdx.x;
    int n0 = nt * 128;

    unsigned sA = (unsigned)__cvta_generic_to_shared(&As[0][0]);
    unsigned sB = (unsigned)__cvta_generic_to_shared(&Bs[0][0]);
    const unsigned ASTAGE = 128 * ASTR * sizeof(__half);
    const unsigned BSTAGE = 16 * BSTR * sizeof(__half);

    int arow = tid >> 1, aseg = tid & 1;
    int brow = tid >> 4, bseg = tid & 15;

    auto load_stage = [&](int j, int st) {
        const __half* asrc = g_Api + ((size_t)j * NROWS + m0) * 16;
        const __half* bsrc = g_Bpi + (size_t)(nt * KSTEPS + j) * 2048;
        cp16s(sA + st * ASTAGE + arow * (ASTR * 2) + aseg * 16,
              asrc + arow * 16 + aseg * 8);
        cp16s(sB + st * BSTAGE + brow * (BSTR * 2) + bseg * 16,
              bsrc + brow * 128 + bseg * 8);
    };

    int warp = tid >> 5;
    int wm = warp & 1, wn = warp >> 1;

    wmma::fragment<wmma::accumulator, 16, 16, 16, float> acc[4][2];
#pragma unroll
    for (int mi = 0; mi < 4; mi++)
#pragma unroll
        for (int ni = 0; ni < 2; ni++) wmma::fill_fragment(acc[mi][ni], 0.f);

#pragma unroll
    for (int p = 0; p < NSTAGE - 1; p++) { load_stage(p, p); cp_commit(); }

    for (int j = 0; j < KSTEPS; j++) {
        int st = j % NSTAGE;
        cp_wait<1>();
        __syncthreads();

        int jn = j + NSTAGE - 1;
        if (jn < KSTEPS) load_stage(jn, jn % NSTAGE);
        cp_commit();

        const __half* Ac = &As[0][0] + st * 128 * ASTR;
        const __half* Bc = &Bs[0][0] + st * 16 * BSTR;

        wmma::fragment<wmma::matrix_a, 16, 16, 16, __half, wmma::row_major> af[4];
        wmma::fragment<wmma::matrix_b, 16, 16, 16, __half, wmma::row_major> bf[2];
#pragma unroll
        for (int mi = 0; mi < 4; mi++)
            wmma::load_matrix_sync(af[mi], Ac + (wm * 64 + mi * 16) * ASTR, ASTR);
#pragma unroll
        for (int ni = 0; ni < 2; ni++)
            wmma::load_matrix_sync(bf[ni], Bc + wn * 32 + ni * 16, BSTR);
#pragma unroll
        for (int mi = 0; mi < 4; mi++)
#pragma unroll
            for (int ni = 0; ni < 2; ni++)
                wmma::mma_sync(acc[mi][ni], af[mi], bf[ni], acc[mi][ni]);
    }

#pragma unroll
    for (int mi = 0; mi < 4; mi++)
#pragma unroll
        for (int ni = 0; ni < 2; ni++) {
            int r0 = m0 + wm * 64 + mi * 16;
            size_t off = (size_t)(r0 >> 5) * 32768
                       + (size_t)(r0 & 31) * 512
                       + n0 + wn * 32 + ni * 16;
            wmma::store_matrix_sync(out + off, acc[mi][ni], 512, wmma::mem_row_major);
        }
}

// ============================================================
// swin GEMM, fused gather: A via LDG->reg->convert->STS double
// buffer (1 sync/iter), B via 4-stage cp.async (unchanged).
// MMA schedule identical to the proven R10 kernel.
// ============================================================
__global__ __launch_bounds__(256, 2) void swin_gemm_f(
    const float* __restrict__ swin, float* __restrict__ out)
{
    __shared__ __align__(16) __half As[2][128 * ASTR];
    __shared__ __align__(16) __half Bs[4][16 * BSTR];
    __shared__ const float* s_ptr[128];

    int tid = threadIdx.x;
    int m0 = blockIdx.y * 128;
    int nt = blockIdx.x;
    int n0 = nt * 128;

    if (tid < 128) {
        int r = m0 + tid;
        int b = r >> 12, n = (r >> 5) & 127, h = r & 31;
        int w = g_fire_w[b * NF + n];
        s_ptr[tid] = swin + (size_t)((b * HH + h) * WW + w) * DSW;
    }

    unsigned sB = (unsigned)__cvta_generic_to_shared(&Bs[0][0]);
    const unsigned BSTAGE = 16 * BSTR * sizeof(__half);

    int arow = tid >> 1, ahalf = tid & 1;     // 2 threads/row, 8 floats each
    int brow = tid >> 4, bseg = tid & 15;

    auto loadB = [&](int j, int st) {
        const __half* bsrc = g_Bsw + (size_t)(nt * KS_SW + j) * 2048;
        cp16s(sB + st * BSTAGE + brow * (BSTR * 2) + bseg * 16,
              bsrc + brow * 128 + bseg * 8);
    };

    float a_reg[8];
    auto ldgA = [&](int j) {
        if (j < 12) {
            const float4* p = (const float4*)(s_ptr[arow] + j * 16 + ahalf * 8);
            float4 v0 = p[0], v1 = p[1];
            a_reg[0] = v0.x; a_reg[1] = v0.y; a_reg[2] = v0.z; a_reg[3] = v0.w;
            a_reg[4] = v1.x; a_reg[5] = v1.y; a_reg[6] = v1.z; a_reg[7] = v1.w;
        } else {                               // bias step: k=192 -> 1.0
            a_reg[0] = (ahalf == 0) ? 1.f : 0.f;
#pragma unroll
            for (int q = 1; q < 8; q++) a_reg[q] = 0.f;
        }
    };
    auto stsA = [&](int j) {
        __half2* d = (__half2*)(&As[j & 1][arow * ASTR + ahalf * 8]);
        d[0] = __float22half2_rn(make_float2(a_reg[0], a_reg[1]));
        d[1] = __float22half2_rn(make_float2(a_reg[2], a_reg[3]));
        d[2] = __float22half2_rn(make_float2(a_reg[4], a_reg[5]));
        d[3] = __float22half2_rn(make_float2(a_reg[6], a_reg[7]));
    };

    int warp = tid >> 5;
    int wm = warp & 1, wn = warp >> 1;

    wmma::fragment<wmma::accumulator, 16, 16, 16, float> acc[4][2];
#pragma unroll
    for (int mi = 0; mi < 4; mi++)
#pragma unroll
        for (int ni = 0; ni < 2; ni++) wmma::fill_fragment(acc[mi][ni], 0.f);

    // prologue: B stages 0..2; A step 0 staged, step 1 in regs
    loadB(0, 0); cp_commit();
    loadB(1, 1); cp_commit();
    loadB(2, 2); cp_commit();
    __syncthreads();                 // s_ptr visible
    ldgA(0); stsA(0);
    ldgA(1);                         // kept in regs until iter 0

    for (int j = 0; j < KS_SW; j++) {
        cp_wait<2>();
        __syncthreads();             // Bs[j%4] + As[j&1] visible

        if (j + 1 < KS_SW) stsA(j + 1);     // other buffer, safe post-sync
        if (j + 2 < KS_SW) ldgA(j + 2);     // latency hidden under MMA j
        if (j + 3 < KS_SW) loadB(j + 3, (j + 3) & 3);
        cp_commit();

        const __half* Ac = &As[j & 1][0];
        const __half* Bc = &Bs[0][0] + (j & 3) * 16 * BSTR;

        wmma::fragment<wmma::matrix_a, 16, 16, 16, __half, wmma::row_major> af[4];
        wmma::fragment<wmma::matrix_b, 16, 16, 16, __half, wmma::row_major> bf[2];
#pragma unroll
        for (int mi = 0; mi < 4; mi++)
            wmma::load_matrix_sync(af[mi], Ac + (wm * 64 + mi * 16) * ASTR, ASTR);
#pragma unroll
        for (int ni = 0; ni < 2; ni++)
            wmma::load_matrix_sync(bf[ni], Bc + wn * 32 + ni * 16, BSTR);
#pragma unroll
        for (int mi = 0; mi < 4; mi++)
#pragma unroll
            for (int ni = 0; ni < 2; ni++)
                wmma::mma_sync(acc[mi][ni], af[mi], bf[ni], acc[mi][ni]);
    }

#pragma unroll
    for (int mi = 0; mi < 4; mi++)
#pragma unroll
        for (int ni = 0; ni < 2; ni++) {
            int r0 = m0 + wm * 64 + mi * 16;
            size_t off = (size_t)(r0 >> 5) * 32768
                       + (size_t)((r0 & 31) + 32) * 512
                       + n0 + wn * 32 + ni * 16;
            wmma::store_matrix_sync(out + off, acc[mi][ni], 512, wmma::mem_row_major);
        }
}

// ============================================================
extern "C" void kernel_launch(void* const* d_in, const int* in_sizes, int n_in,
                              void* d_out, int out_size)
{
    const float* fs      = (const float*)d_in[0];
    const float* swin    = (const float*)d_in[1];
    const float* pitch   = (const float*)d_in[2];
    const int*   tlen    = (const int*)  d_in[3];
    const float* conv_w  = (const float*)d_in[4];
    const float* ln_w    = (const float*)d_in[5];
    const float* ln_b    = (const float*)d_in[6];
    const float* dense_w = (const float*)d_in[7];
    const float* dense_b = (const float*)d_in[8];
    const float* proj_w  = (const float*)d_in[9];
    const float* proj_b  = (const float*)d_in[10];
    const float* pitch_w = (const float*)d_in[11];
    const float* pitch_b = (const float*)d_in[12];
    const float* swin_w  = (const float*)d_in[13];
    const float* swin_b  = (const float*)d_in[14];
    float* out = (float*)d_out;

    static cudaStream_t s1 = nullptr;
    static cudaEvent_t ev_root = nullptr, ev_b = nullptr,
                       ev_fires = nullptr, ev_end = nullptr;
    static bool init_tried = false;
    if (!init_tried) {
        init_tried = true;
        if (cudaStreamCreateWithFlags(&s1, cudaStreamNonBlocking) != cudaSuccess) s1 = nullptr;
        if (s1) {
            if (cudaEventCreateWithFlags(&ev_root,  cudaEventDisableTiming) != cudaSuccess ||
                cudaEventCreateWithFlags(&ev_b,     cudaEventDisableTiming) != cudaSuccess ||
                cudaEventCreateWithFlags(&ev_fires, cudaEventDisableTiming) != cudaSuccess ||
                cudaEventCreateWithFlags(&ev_end,   cudaEventDisableTiming) != cudaSuccess) {
                s1 = nullptr;
            }
        }
    }

    dim3 grid(NTILES, NROWS / 128);   // (4, 512)

    if (s1) {
        cudaEventRecord(ev_root, 0);
        cudaStreamWaitEvent(s1, ev_root, 0);

        // s1: independent pitch chain (+ B packs)
        pack_b_kernel<<<(NTILES * (KS_SW + KS_PI) * 2048 + 255) / 256, 256, 0, s1>>>(
            swin_w, swin_b, pitch_w, pitch_b);
        cudaEventRecord(ev_b, s1);
        pack_a_pitch<<<NROWS / 8, 256, 0, s1>>>(pitch);
        pitch_gemm<<<grid, 256, 0, s1>>>(out);

        // s0: alpha -> fires -> fused swin gemm
        alpha_kernel<<<750, 256>>>(fs, conv_w, ln_w, ln_b,
                                   dense_w, dense_b, proj_w, proj_b,
                                   out + ALPHA_OFF);
        fires_kernel<<<BB, 1024>>>(out + ALPHA_OFF, tlen);
        cudaEventRecord(ev_fires, 0);

        cudaStreamWaitEvent(0, ev_b, 0);          // g_Bsw ready
        swin_gemm_f<<<grid, 256>>>(swin, out);

        // qty overlapped on s1
        cudaStreamWaitEvent(s1, ev_fires, 0);
        qty_kernel<<<1, 32, 0, s1>>>(out + QTY_OFF);

        cudaEventRecord(ev_end, s1);
        cudaStreamWaitEvent(0, ev_end, 0);
    } else {
        alpha_kernel<<<750, 256>>>(fs, conv_w, ln_w, ln_b,
                                   dense_w, dense_b, proj_w, proj_b,
                                   out + ALPHA_OFF);
        fires_kernel<<<BB, 1024>>>(out + ALPHA_OFF, tlen);
        qty_kernel<<<1, 32>>>(out + QTY_OFF);
        pack_b_kernel<<<(NTILES * (KS_SW + KS_PI) * 2048 + 255) / 256, 256>>>(
            swin_w, swin_b, pitch_w, pitch_b);
        pack_a_pitch<<<NROWS / 8, 256>>>(pitch);
        pitch_gemm<<<grid, 256>>>(out);
        swin_gemm_f<<<grid, 256>>>(swin, out);
    }
}

// round 14
// speedup vs baseline: 1.0996x; 1.0996x over previous
#include <cuda_runtime.h>
#include <cuda_fp16.h>
#include <mma.h>
#include <cstdint>
using namespace nvcuda;

// ---------------- problem constants ----------------
#define BB    16
#define TT    3000
#define CC    32
#define HH    32
#define WW    375
#define DSW   192
#define PP    32
#define DMODEL 512
#define HID   128
#define NF    128

#define ACOUSTIC_SIZE (BB * NF * 64 * DMODEL)
#define ALPHA_OFF     ACOUSTIC_SIZE
#define QTY_OFF       (ALPHA_OFF + BB * TT)

#define NROWS   (BB * NF * 32)     // 65536 GEMM rows
#define KS_SW   13                 // swin k-steps of 16
#define KS_PI   3                  // pitch k-steps
#define NTILES  4                  // DMODEL / 128

// ---------------- scratch ----------------
__device__ int    g_fire_w[BB * NF];
__device__ float  g_qdiff[BB];
__device__ __align__(256) __half g_Asw[(size_t)KS_SW * NROWS * 16];
__device__ __align__(256) __half g_Api[(size_t)KS_PI * NROWS * 16];
__device__ __align__(256) __half g_Bsw[NTILES * KS_SW * 2048];
__device__ __align__(256) __half g_Bpi[NTILES * KS_PI * 2048];

// ---------------- helpers ----------------
__device__ __forceinline__ float warp_sum(float v) {
#pragma unroll
    for (int o = 16; o > 0; o >>= 1) v += __shfl_xor_sync(0xffffffffu, v, o);
    return v;
}
__device__ __forceinline__ void cp16s(unsigned saddr, const void* g) {
    asm volatile("cp.async.cg.shared.global [%0], [%1], 16;" :: "r"(saddr), "l"(g));
}
__device__ __forceinline__ void cp_commit() {
    asm volatile("cp.async.commit_group;" ::: "memory");
}
template <int N>
__device__ __forceinline__ void cp_wait() {
    asm volatile("cp.async.wait_group %0;" :: "n"(N) : "memory");
}

// ============================================================
// Kernel 1: alpha — 8 consecutive t per warp, float4 weight LDS
// ============================================================
__global__ __launch_bounds__(256) void alpha_kernel(
    const float* __restrict__ fs,
    const float* __restrict__ conv_w,
    const float* __restrict__ ln_w,  const float* __restrict__ ln_b,
    const float* __restrict__ dense_w, const float* __restrict__ dense_b,
    const float* __restrict__ proj_w,  const float* __restrict__ proj_b,
    float* __restrict__ alpha_out)
{
    __shared__ float4 s_dw4[CC * 32];
    __shared__ float4 s_db4[32], s_pw4[32];
    __shared__ float  s_cw[CC * 3], s_lnw[CC], s_lnb[CC];

    int tid = threadIdx.x;
    for (int i = tid; i < CC * HID; i += 256) {
        int cc = i >> 7, j = i & 127;
        int q = j >> 5, l = j & 31;
        ((float*)s_dw4)[cc * 128 + l * 4 + q] = dense_w[i];
    }
    if (tid < HID) {
        int q = tid >> 5, l = tid & 31;
        ((float*)s_db4)[l * 4 + q] = dense_b[tid];
        ((float*)s_pw4)[l * 4 + q] = proj_w[tid];
    }
    if (tid < CC * 3) s_cw[tid] = conv_w[tid];
    if (tid < CC) { s_lnw[tid] = ln_w[tid]; s_lnb[tid] = ln_b[tid]; }
    __syncthreads();

    int warp = tid >> 5, lane = tid & 31;
    int g = blockIdx.x * 8 + warp;
    int t0 = (g * 8) % TT;
    int b  = (g * 8) / TT;

    const float* base = fs + ((size_t)b * TT + t0) * CC + lane;
    float xv[10];
#pragma unroll
    for (int j = 0; j < 10; j++) {
        int t = t0 - 1 + j;
        xv[j] = (t >= 0 && t < TT) ? base[(j - 1) * CC] : 0.f;
    }

    float cw0 = s_cw[lane * 3], cw1 = s_cw[lane * 3 + 1], cw2 = s_cw[lane * 3 + 2];
    float lnw = s_lnw[lane], lnb = s_lnb[lane];

    float xn[8];
#pragma unroll
    for (int i = 0; i < 8; i++) {
        float x = fmaf(cw0, xv[i], fmaf(cw1, xv[i + 1], cw2 * xv[i + 2])) + xv[i + 1];
        float mu  = warp_sum(x) * (1.f / CC);
        float d   = x - mu;
        float var = warp_sum(d * d) * (1.f / CC);
        xn[i] = d * rsqrtf(var + 1e-5f) * lnw + lnb;
    }

    float4 db = s_db4[lane];
    float4 h[8] = {db, db, db, db, db, db, db, db};
#pragma unroll
    for (int cc = 0; cc < CC; cc++) {
        float4 w = s_dw4[cc * 32 + lane];
#pragma unroll
        for (int i = 0; i < 8; i++) {
            float v = __shfl_sync(0xffffffffu, xn[i], cc);
            h[i].x = fmaf(v, w.x, h[i].x);
            h[i].y = fmaf(v, w.y, h[i].y);
            h[i].z = fmaf(v, w.z, h[i].z);
            h[i].w = fmaf(v, w.w, h[i].w);
        }
    }

    float4 pw = s_pw4[lane];
    float ps[8];
#pragma unroll
    for (int i = 0; i < 8; i++) {
        float p = fmaxf(h[i].x, 0.f) * pw.x + fmaxf(h[i].y, 0.f) * pw.y
                + fmaxf(h[i].z, 0.f) * pw.z + fmaxf(h[i].w, 0.f) * pw.w;
        ps[i] = warp_sum(p);
    }

    if (lane < 8) {
        float psel = ps[0];
#pragma unroll
        for (int i = 1; i < 8; i++) if (lane == i) psel = ps[i];
        float a  = psel + proj_b[0];
        float sp = fmaxf(a, 0.f) + log1pf(expf(-fabsf(a)));
        alpha_out[(size_t)b * TT + t0 + lane] = sp;
    }
}

// ============================================================
// Kernel 2: fires (warp-scan, 2 barriers)
// ============================================================
__global__ __launch_bounds__(1024) void fires_kernel(
    const float* __restrict__ alpha, const int* __restrict__ tlen)
{
    __shared__ int   s_wsum[32];
    __shared__ int   s_frame[NF];
    __shared__ float s_red[32];

    int b = blockIdx.x, tid = threadIdx.x;
    int lane = tid & 31, warp = tid >> 5;
    if (tid < NF) s_frame[tid] = TT - 1;

    const float* arow = alpha + (size_t)b * TT;
    int base = tid * 3;
    int pred[3] = {0, 0, 0};
    int mycnt = 0; float onset = 0.f;
#pragma unroll
    for (int i = 0; i < 3; i++) {
        int t = base + i;
        if (t < TT) {
            float a = arow[t];
            int pr = (a > 1.0f);
            pred[i] = pr; mycnt += pr;
            onset += 1.f / (1.f + expf(-(a - 1.0f) * 10.f));
        }
    }
    int scan = mycnt;
#pragma unroll
    for (int o = 1; o < 32; o <<= 1) {
        int v = __shfl_up_sync(0xffffffffu, scan, o);
        if (lane >= o) scan += v;
    }
    if (lane == 31) s_wsum[warp] = scan;
    float os = warp_sum(onset);
    if (lane == 0) s_red[warp] = os;
    __syncthreads();
    if (warp == 0) {
        int ws = s_wsum[lane];
#pragma unroll
        for (int o = 1; o < 32; o <<= 1) {
            int v = __shfl_up_sync(0xffffffffu, ws, o);
            if (lane >= o) ws += v;
        }
        s_wsum[lane] = ws;
        float v = warp_sum(s_red[lane]);
        if (lane == 0) g_qdiff[b] = fabsf(v - (float)tlen[b]);
    }
    __syncthreads();
    int c = scan - mycnt + (warp > 0 ? s_wsum[warp - 1] : 0);
#pragma unroll
    for (int i = 0; i < 3; i++) {
        if (pred[i]) {
            c += 1;
            if (c <= NF) s_frame[c - 1] = base + i;
        }
    }
    __syncthreads();
    if (tid < NF) g_fire_w[b * NF + tid] = s_frame[tid] >> 3;
}

__global__ void qty_kernel(float* __restrict__ out) {
    int tid = threadIdx.x;
    float v = (tid < BB) ? g_qdiff[tid] : 0.f;
    v = warp_sum(v);
    if (tid == 0) out[0] = v * (1.f / BB);
}

// ============================================================
// Packing kernels (fp16 RN, bias row folded, k-step blocked)
// ============================================================
__global__ __launch_bounds__(256) void pack_b_kernel(
    const float* __restrict__ sw_w, const float* __restrict__ sw_b,
    const float* __restrict__ pi_w, const float* __restrict__ pi_b)
{
    int idx = blockIdx.x * 256 + threadIdx.x;
    const int SWTOT = NTILES * KS_SW * 2048;
    if (idx < SWTOT) {
        int nt = idx / (KS_SW * 2048);
        int rem = idx % (KS_SW * 2048);
        int j = rem / 2048, e = rem % 2048;
        int kr = e >> 7, n = e & 127;
        int k = j * 16 + kr;
        float v = (k < DSW) ? sw_w[k * DMODEL + nt * 128 + n]
                : (k == DSW ? sw_b[nt * 128 + n] : 0.f);
        g_Bsw[idx] = __float2half_rn(v);
    } else {
        int x = idx - SWTOT;
        if (x >= NTILES * KS_PI * 2048) return;
        int nt = x / (KS_PI * 2048);
        int rem = x % (KS_PI * 2048);
        int j = rem / 2048, e = rem % 2048;
        int kr = e >> 7, n = e & 127;
        int k = j * 16 + kr;
        float v = (k < 32) ? pi_w[k * DMODEL + nt * 128 + n]
                : (k == 32 ? pi_b[nt * 128 + n] : 0.f);
        g_Bpi[x] = __float2half_rn(v);
    }
}

__global__ __launch_bounds__(256) void pack_a_pitch(const float* __restrict__ pitch)
{
    int warp = threadIdx.x >> 5, lane = threadIdx.x & 31;
    int r = blockIdx.x * 8 + warp;
    float v = pitch[(size_t)r * 32 + lane];
    g_Api[((size_t)(lane >> 4) * NROWS + r) * 16 + (lane & 15)] = __float2half_rn(v);
    if (lane < 16)
        g_Api[((size_t)2 * NROWS + r) * 16 + lane] =
            __float2half_rn(lane == 0 ? 1.f : 0.f);
}

__global__ __launch_bounds__(256) void pack_a_swin(const float* __restrict__ swin)
{
    int warp = threadIdx.x >> 5, lane = threadIdx.x & 31;
    int r = blockIdx.x * 8 + warp;
    int b = r >> 12, n = (r >> 5) & 127, h = r & 31;
    int w = g_fire_w[b * NF + n];
    const float* src = swin + (size_t)((b * HH + h) * WW + w) * DSW;
#pragma unroll
    for (int j = 0; j < 6; j++) {
        int k = j * 32 + lane;
        float v = src[k];
        g_Asw[((size_t)(k >> 4) * NROWS + r) * 16 + (k & 15)] = __float2half_rn(v);
    }
    if (lane < 16)
        g_Asw[((size_t)12 * NROWS + r) * 16 + lane] =
            __float2half_rn(lane == 0 ? 1.f : 0.f);
}

// ============================================================
// fp16 wmma GEMM: 128x128 tile, k-step(16) multistage cp.async
// (R10-proven schedule; ONLY change vs R10: swin uses NSTAGE=5)
// ============================================================
#define ASTR 24
#define BSTR 136

template<int KSTEPS, int NSTAGE, int SLOTBASE>
__global__ __launch_bounds__(256, 2) void gemm_fp16(float* __restrict__ out)
{
    __shared__ __align__(16) __half As[NSTAGE][128 * ASTR];
    __shared__ __align__(16) __half Bs[NSTAGE][16 * BSTR];

    const __half* __restrict__ Apk = (SLOTBASE == 0) ? g_Api : g_Asw;
    const __half* __restrict__ Bpk = (SLOTBASE == 0) ? g_Bpi : g_Bsw;

    int tid = threadIdx.x;
    int m0 = blockIdx.y * 128;
    int nt = blockIdx.x;
    int n0 = nt * 128;

    unsigned sA = (unsigned)__cvta_generic_to_shared(&As[0][0]);
    unsigned sB = (unsigned)__cvta_generic_to_shared(&Bs[0][0]);
    const unsigned ASTAGE = 128 * ASTR * sizeof(__half);
    const unsigned BSTAGE = 16 * BSTR * sizeof(__half);

    int arow = tid >> 1, aseg = tid & 1;
    int brow = tid >> 4, bseg = tid & 15;

    auto load_stage = [&](int j, int st) {
        const __half* asrc = Apk + ((size_t)j * NROWS + m0) * 16;
        const __half* bsrc = Bpk + (size_t)(nt * KSTEPS + j) * 2048;
        cp16s(sA + st * ASTAGE + arow * (ASTR * 2) + aseg * 16,
              asrc + arow * 16 + aseg * 8);
        cp16s(sB + st * BSTAGE + brow * (BSTR * 2) + bseg * 16,
              bsrc + brow * 128 + bseg * 8);
    };

    int warp = tid >> 5;
    int wm = warp & 1, wn = warp >> 1;

    wmma::fragment<wmma::accumulator, 16, 16, 16, float> acc[4][2];
#pragma unroll
    for (int mi = 0; mi < 4; mi++)
#pragma unroll
        for (int ni = 0; ni < 2; ni++) wmma::fill_fragment(acc[mi][ni], 0.f);

#pragma unroll
    for (int p = 0; p < NSTAGE - 1; p++) {
        if (p < KSTEPS) load_stage(p, p);
        cp_commit();
    }

    for (int j = 0; j < KSTEPS; j++) {
        int st = j % NSTAGE;
        cp_wait<NSTAGE - 2>();
        __syncthreads();

        int jn = j + NSTAGE - 1;
        if (jn < KSTEPS) load_stage(jn, jn % NSTAGE);
        cp_commit();

        const __half* Ac = &As[0][0] + st * 128 * ASTR;
        const __half* Bc = &Bs[0][0] + st * 16 * BSTR;

        wmma::fragment<wmma::matrix_a, 16, 16, 16, __half, wmma::row_major> af[4];
        wmma::fragment<wmma::matrix_b, 16, 16, 16, __half, wmma::row_major> bf[2];
#pragma unroll
        for (int mi = 0; mi < 4; mi++)
            wmma::load_matrix_sync(af[mi], Ac + (wm * 64 + mi * 16) * ASTR, ASTR);
#pragma unroll
        for (int ni = 0; ni < 2; ni++)
            wmma::load_matrix_sync(bf[ni], Bc + wn * 32 + ni * 16, BSTR);
#pragma unroll
        for (int mi = 0; mi < 4; mi++)
#pragma unroll
            for (int ni = 0; ni < 2; ni++)
                wmma::mma_sync(acc[mi][ni], af[mi], bf[ni], acc[mi][ni]);
    }

#pragma unroll
    for (int mi = 0; mi < 4; mi++)
#pragma unroll
        for (int ni = 0; ni < 2; ni++) {
            int r0 = m0 + wm * 64 + mi * 16;
            size_t off = (size_t)(r0 >> 5) * 32768
                       + (size_t)((r0 & 31) + SLOTBASE) * 512
                       + n0 + wn * 32 + ni * 16;
            wmma::store_matrix_sync(out + off, acc[mi][ni], 512, wmma::mem_row_major);
        }
}

// ============================================================
extern "C" void kernel_launch(void* const* d_in, const int* in_sizes, int n_in,
                              void* d_out, int out_size)
{
    const float* fs      = (const float*)d_in[0];
    const float* swin    = (const float*)d_in[1];
    const float* pitch   = (const float*)d_in[2];
    const int*   tlen    = (const int*)  d_in[3];
    const float* conv_w  = (const float*)d_in[4];
    const float* ln_w    = (const float*)d_in[5];
    const float* ln_b    = (const float*)d_in[6];
    const float* dense_w = (const float*)d_in[7];
    const float* dense_b = (const float*)d_in[8];
    const float* proj_w  = (const float*)d_in[9];
    const float* proj_b  = (const float*)d_in[10];
    const float* pitch_w = (const float*)d_in[11];
    const float* pitch_b = (const float*)d_in[12];
    const float* swin_w  = (const float*)d_in[13];
    const float* swin_b  = (const float*)d_in[14];
    float* out = (float*)d_out;

    static cudaStream_t s1 = nullptr;
    static cudaEvent_t ev_root = nullptr, ev_fires = nullptr, ev_end = nullptr;
    static bool init_tried = false;
    if (!init_tried) {
        init_tried = true;
        if (cudaStreamCreateWithFlags(&s1, cudaStreamNonBlocking) != cudaSuccess) s1 = nullptr;
        if (s1) {
            if (cudaEventCreateWithFlags(&ev_root,  cudaEventDisableTiming) != cudaSuccess ||
                cudaEventCreateWithFlags(&ev_fires, cudaEventDisableTiming) != cudaSuccess ||
                cudaEventCreateWithFlags(&ev_end,   cudaEventDisableTiming) != cudaSuccess) {
                s1 = nullptr;
            }
        }
    }

    dim3 grid(NTILES, NROWS / 128);   // (4, 512)

    if (s1) {
        cudaEventRecord(ev_root, 0);
        cudaStreamWaitEvent(s1, ev_root, 0);

        // s1: independent pitch chain
        pack_b_kernel<<<(NTILES * (KS_SW + KS_PI) * 2048 + 255) / 256, 256, 0, s1>>>(
            swin_w, swin_b, pitch_w, pitch_b);
        pack_a_pitch<<<NROWS / 8, 256, 0, s1>>>(pitch);
        gemm_fp16<KS_PI, 3, 0><<<grid, 256, 0, s1>>>(out);

        // s0: main chain
        alpha_kernel<<<750, 256>>>(fs, conv_w, ln_w, ln_b,
                                   dense_w, dense_b, proj_w, proj_b,
                                   out + ALPHA_OFF);
        fires_kernel<<<BB, 1024>>>(out + ALPHA_OFF, tlen);
        cudaEventRecord(ev_fires, 0);
        pack_a_swin<<<NROWS / 8, 256>>>(swin);

        // qty overlapped on s1
        cudaStreamWaitEvent(s1, ev_fires, 0);
        qty_kernel<<<1, 32, 0, s1>>>(out + QTY_OFF);

        gemm_fp16<KS_SW, 5, 32><<<grid, 256>>>(out);

        cudaEventRecord(ev_end, s1);
        cudaStreamWaitEvent(0, ev_end, 0);
    } else {
        alpha_kernel<<<750, 256>>>(fs, conv_w, ln_w, ln_b,
                                   dense_w, dense_b, proj_w, proj_b,
                                   out + ALPHA_OFF);
        fires_kernel<<<BB, 1024>>>(out + ALPHA_OFF, tlen);
        qty_kernel<<<1, 32>>>(out + QTY_OFF);
        pack_b_kernel<<<(NTILES * (KS_SW + KS_PI) * 2048 + 255) / 256, 256>>>(
            swin_w, swin_b, pitch_w, pitch_b);
        pack_a_pitch<<<NROWS / 8, 256>>>(pitch);
        pack_a_swin<<<NROWS / 8, 256>>>(swin);
        gemm_fp16<KS_SW, 5, 32><<<grid, 256>>>(out);
        gemm_fp16<KS_PI, 3, 0><<<grid, 256>>>(out);
    }
}

// round 15
// speedup vs baseline: 1.1162x; 1.0151x over previous
#include <cuda_runtime.h>
#include <cuda_fp16.h>
#include <mma.h>
#include <cstdint>
using namespace nvcuda;

// ---------------- problem constants ----------------
#define BB    16
#define TT    3000
#define CC    32
#define HH    32
#define WW    375
#define DSW   192
#define PP    32
#define DMODEL 512
#define HID   128
#define NF    128

#define ACOUSTIC_SIZE (BB * NF * 64 * DMODEL)
#define ALPHA_OFF     ACOUSTIC_SIZE
#define QTY_OFF       (ALPHA_OFF + BB * TT)

#define NROWS   (BB * NF * 32)     // 65536 GEMM rows
#define KS_SW   13                 // swin k-steps of 16
#define KS_PI   3                  // pitch k-steps
#define NTILES  4                  // DMODEL / 128

// ---------------- scratch ----------------
__device__ int    g_fire_w[BB * NF];
__device__ float  g_qdiff[BB];
__device__ __align__(256) __half g_Asw[(size_t)KS_SW * NROWS * 16];
__device__ __align__(256) __half g_Api[(size_t)KS_PI * NROWS * 16];
__device__ __align__(256) __half g_Bsw[NTILES * KS_SW * 2048];
__device__ __align__(256) __half g_Bpi[NTILES * KS_PI * 2048];

// ---------------- helpers ----------------
__device__ __forceinline__ float warp_sum(float v) {
#pragma unroll
    for (int o = 16; o > 0; o >>= 1) v += __shfl_xor_sync(0xffffffffu, v, o);
    return v;
}
__device__ __forceinline__ void cp16s(unsigned saddr, const void* g) {
    asm volatile("cp.async.cg.shared.global [%0], [%1], 16;" :: "r"(saddr), "l"(g));
}
__device__ __forceinline__ void cp_commit() {
    asm volatile("cp.async.commit_group;" ::: "memory");
}
template <int N>
__device__ __forceinline__ void cp_wait() {
    asm volatile("cp.async.wait_group %0;" :: "n"(N) : "memory");
}

// ============================================================
// Kernel 1: alpha — 8 consecutive t per warp, float4 weight LDS
// ============================================================
__global__ __launch_bounds__(256) void alpha_kernel(
    const float* __restrict__ fs,
    const float* __restrict__ conv_w,
    const float* __restrict__ ln_w,  const float* __restrict__ ln_b,
    const float* __restrict__ dense_w, const float* __restrict__ dense_b,
    const float* __restrict__ proj_w,  const float* __restrict__ proj_b,
    float* __restrict__ alpha_out)
{
    __shared__ float4 s_dw4[CC * 32];
    __shared__ float4 s_db4[32], s_pw4[32];
    __shared__ float  s_cw[CC * 3], s_lnw[CC], s_lnb[CC];

    int tid = threadIdx.x;
    for (int i = tid; i < CC * HID; i += 256) {
        int cc = i >> 7, j = i & 127;
        int q = j >> 5, l = j & 31;
        ((float*)s_dw4)[cc * 128 + l * 4 + q] = dense_w[i];
    }
    if (tid < HID) {
        int q = tid >> 5, l = tid & 31;
        ((float*)s_db4)[l * 4 + q] = dense_b[tid];
        ((float*)s_pw4)[l * 4 + q] = proj_w[tid];
    }
    if (tid < CC * 3) s_cw[tid] = conv_w[tid];
    if (tid < CC) { s_lnw[tid] = ln_w[tid]; s_lnb[tid] = ln_b[tid]; }
    __syncthreads();

    int warp = tid >> 5, lane = tid & 31;
    int g = blockIdx.x * 8 + warp;
    int t0 = (g * 8) % TT;
    int b  = (g * 8) / TT;

    const float* base = fs + ((size_t)b * TT + t0) * CC + lane;
    float xv[10];
#pragma unroll
    for (int j = 0; j < 10; j++) {
        int t = t0 - 1 + j;
        xv[j] = (t >= 0 && t < TT) ? base[(j - 1) * CC] : 0.f;
    }

    float cw0 = s_cw[lane * 3], cw1 = s_cw[lane * 3 + 1], cw2 = s_cw[lane * 3 + 2];
    float lnw = s_lnw[lane], lnb = s_lnb[lane];

    float xn[8];
#pragma unroll
    for (int i = 0; i < 8; i++) {
        float x = fmaf(cw0, xv[i], fmaf(cw1, xv[i + 1], cw2 * xv[i + 2])) + xv[i + 1];
        float mu  = warp_sum(x) * (1.f / CC);
        float d   = x - mu;
        float var = warp_sum(d * d) * (1.f / CC);
        xn[i] = d * rsqrtf(var + 1e-5f) * lnw + lnb;
    }

    float4 db = s_db4[lane];
    float4 h[8] = {db, db, db, db, db, db, db, db};
#pragma unroll
    for (int cc = 0; cc < CC; cc++) {
        float4 w = s_dw4[cc * 32 + lane];
#pragma unroll
        for (int i = 0; i < 8; i++) {
            float v = __shfl_sync(0xffffffffu, xn[i], cc);
            h[i].x = fmaf(v, w.x, h[i].x);
            h[i].y = fmaf(v, w.y, h[i].y);
            h[i].z = fmaf(v, w.z, h[i].z);
            h[i].w = fmaf(v, w.w, h[i].w);
        }
    }

    float4 pw = s_pw4[lane];
    float ps[8];
#pragma unroll
    for (int i = 0; i < 8; i++) {
        float p = fmaxf(h[i].x, 0.f) * pw.x + fmaxf(h[i].y, 0.f) * pw.y
                + fmaxf(h[i].z, 0.f) * pw.z + fmaxf(h[i].w, 0.f) * pw.w;
        ps[i] = warp_sum(p);
    }

    if (lane < 8) {
        float psel = ps[0];
#pragma unroll
        for (int i = 1; i < 8; i++) if (lane == i) psel = ps[i];
        float a  = psel + proj_b[0];
        float sp = fmaxf(a, 0.f) + log1pf(expf(-fabsf(a)));
        alpha_out[(size_t)b * TT + t0 + lane] = sp;
    }
}

// ============================================================
// Kernel 2: fires (warp-scan, 2 barriers)
// ============================================================
__global__ __launch_bounds__(1024) void fires_kernel(
    const float* __restrict__ alpha, const int* __restrict__ tlen)
{
    __shared__ int   s_wsum[32];
    __shared__ int   s_frame[NF];
    __shared__ float s_red[32];

    int b = blockIdx.x, tid = threadIdx.x;
    int lane = tid & 31, warp = tid >> 5;
    if (tid < NF) s_frame[tid] = TT - 1;

    const float* arow = alpha + (size_t)b * TT;
    int base = tid * 3;
    int pred[3] = {0, 0, 0};
    int mycnt = 0; float onset = 0.f;
#pragma unroll
    for (int i = 0; i < 3; i++) {
        int t = base + i;
        if (t < TT) {
            float a = arow[t];
            int pr = (a > 1.0f);
            pred[i] = pr; mycnt += pr;
            onset += 1.f / (1.f + expf(-(a - 1.0f) * 10.f));
        }
    }
    int scan = mycnt;
#pragma unroll
    for (int o = 1; o < 32; o <<= 1) {
        int v = __shfl_up_sync(0xffffffffu, scan, o);
        if (lane >= o) scan += v;
    }
    if (lane == 31) s_wsum[warp] = scan;
    float os = warp_sum(onset);
    if (lane == 0) s_red[warp] = os;
    __syncthreads();
    if (warp == 0) {
        int ws = s_wsum[lane];
#pragma unroll
        for (int o = 1; o < 32; o <<= 1) {
            int v = __shfl_up_sync(0xffffffffu, ws, o);
            if (lane >= o) ws += v;
        }
        s_wsum[lane] = ws;
        float v = warp_sum(s_red[lane]);
        if (lane == 0) g_qdiff[b] = fabsf(v - (float)tlen[b]);
    }
    __syncthreads();
    int c = scan - mycnt + (warp > 0 ? s_wsum[warp - 1] : 0);
#pragma unroll
    for (int i = 0; i < 3; i++) {
        if (pred[i]) {
            c += 1;
            if (c <= NF) s_frame[c - 1] = base + i;
        }
    }
    __syncthreads();
    if (tid < NF) g_fire_w[b * NF + tid] = s_frame[tid] >> 3;
}

__global__ void qty_kernel(float* __restrict__ out) {
    int tid = threadIdx.x;
    float v = (tid < BB) ? g_qdiff[tid] : 0.f;
    v = warp_sum(v);
    if (tid == 0) out[0] = v * (1.f / BB);
}

// ============================================================
// Packing kernels (fp16 RN, bias row folded, k-step blocked)
// ============================================================
__global__ __launch_bounds__(256) void pack_b_kernel(
    const float* __restrict__ sw_w, const float* __restrict__ sw_b,
    const float* __restrict__ pi_w, const float* __restrict__ pi_b)
{
    int idx = blockIdx.x * 256 + threadIdx.x;
    const int SWTOT = NTILES * KS_SW * 2048;
    if (idx < SWTOT) {
        int nt = idx / (KS_SW * 2048);
        int rem = idx % (KS_SW * 2048);
        int j = rem / 2048, e = rem % 2048;
        int kr = e >> 7, n = e & 127;
        int k = j * 16 + kr;
        float v = (k < DSW) ? sw_w[k * DMODEL + nt * 128 + n]
                : (k == DSW ? sw_b[nt * 128 + n] : 0.f);
        g_Bsw[idx] = __float2half_rn(v);
    } else {
        int x = idx - SWTOT;
        if (x >= NTILES * KS_PI * 2048) return;
        int nt = x / (KS_PI * 2048);
        int rem = x % (KS_PI * 2048);
        int j = rem / 2048, e = rem % 2048;
        int kr = e >> 7, n = e & 127;
        int k = j * 16 + kr;
        float v = (k < 32) ? pi_w[k * DMODEL + nt * 128 + n]
                : (k == 32 ? pi_b[nt * 128 + n] : 0.f);
        g_Bpi[x] = __float2half_rn(v);
    }
}

__global__ __launch_bounds__(256) void pack_a_pitch(const float* __restrict__ pitch)
{
    int warp = threadIdx.x >> 5, lane = threadIdx.x & 31;
    int r = blockIdx.x * 8 + warp;
    float v = pitch[(size_t)r * 32 + lane];
    g_Api[((size_t)(lane >> 4) * NROWS + r) * 16 + (lane & 15)] = __float2half_rn(v);
    if (lane < 16)
        g_Api[((size_t)2 * NROWS + r) * 16 + lane] =
            __float2half_rn(lane == 0 ? 1.f : 0.f);
}

// vectorized swin A pack: float4 loads, half2-pair (8B) stores
// row r: 48 float4 src; j-th float4 -> kstep j>>2, halves (j&3)*4..+3
__global__ __launch_bounds__(256) void pack_a_swin(const float* __restrict__ swin)
{
    int warp = threadIdx.x >> 5, lane = threadIdx.x & 31;
    int r = blockIdx.x * 8 + warp;
    int b = r >> 12, n = (r >> 5) & 127, h = r & 31;
    int w = g_fire_w[b * NF + n];
    const float4* src4 = (const float4*)(swin
        + (size_t)((b * HH + h) * WW + w) * DSW);   // 768B-aligned rows

#pragma unroll
    for (int t = 0; t < 2; t++) {
        int j = lane + t * 32;
        if (j < 48) {
            float4 v = src4[j];
            int kstep = j >> 2;
            int off = (j & 3) * 4;
            __half2* d = (__half2*)(g_Asw + ((size_t)kstep * NROWS + r) * 16 + off);
            d[0] = __float22half2_rn(make_float2(v.x, v.y));
            d[1] = __float22half2_rn(make_float2(v.z, v.w));
        }
    }
    // bias k-step 12: halves {1, 0, 0, ..., 0}
    if (lane < 4) {
        __half2* d = (__half2*)(g_Asw + ((size_t)12 * NROWS + r) * 16 + lane * 4);
        __half2 z = __floats2half2_rn(0.f, 0.f);
        d[0] = (lane == 0) ? __floats2half2_rn(1.f, 0.f) : z;
        d[1] = z;
    }
}

// ============================================================
// fp16 wmma GEMM: 128x128 tile, k-step(16) multistage cp.async
// (R10-proven; swin NSTAGE=4, pitch NSTAGE=3)
// ============================================================
#define ASTR 24
#define BSTR 136

template<int KSTEPS, int NSTAGE, int SLOTBASE>
__global__ __launch_bounds__(256, 2) void gemm_fp16(float* __restrict__ out)
{
    __shared__ __align__(16) __half As[NSTAGE][128 * ASTR];
    __shared__ __align__(16) __half Bs[NSTAGE][16 * BSTR];

    const __half* __restrict__ Apk = (SLOTBASE == 0) ? g_Api : g_Asw;
    const __half* __restrict__ Bpk = (SLOTBASE == 0) ? g_Bpi : g_Bsw;

    int tid = threadIdx.x;
    int m0 = blockIdx.y * 128;
    int nt = blockIdx.x;
    int n0 = nt * 128;

    unsigned sA = (unsigned)__cvta_generic_to_shared(&As[0][0]);
    unsigned sB = (unsigned)__cvta_generic_to_shared(&Bs[0][0]);
    const unsigned ASTAGE = 128 * ASTR * sizeof(__half);
    const unsigned BSTAGE = 16 * BSTR * sizeof(__half);

    int arow = tid >> 1, aseg = tid & 1;
    int brow = tid >> 4, bseg = tid & 15;

    auto load_stage = [&](int j, int st) {
        const __half* asrc = Apk + ((size_t)j * NROWS + m0) * 16;
        const __half* bsrc = Bpk + (size_t)(nt * KSTEPS + j) * 2048;
        cp16s(sA + st * ASTAGE + arow * (ASTR * 2) + aseg * 16,
              asrc + arow * 16 + aseg * 8);
        cp16s(sB + st * BSTAGE + brow * (BSTR * 2) + bseg * 16,
              bsrc + brow * 128 + bseg * 8);
    };

    int warp = tid >> 5;
    int wm = warp & 1, wn = warp >> 1;

    wmma::fragment<wmma::accumulator, 16, 16, 16, float> acc[4][2];
#pragma unroll
    for (int mi = 0; mi < 4; mi++)
#pragma unroll
        for (int ni = 0; ni < 2; ni++) wmma::fill_fragment(acc[mi][ni], 0.f);

#pragma unroll
    for (int p = 0; p < NSTAGE - 1; p++) { load_stage(p, p); cp_commit(); }

    for (int j = 0; j < KSTEPS; j++) {
        int st = j % NSTAGE;
        cp_wait<NSTAGE - 2>();
        __syncthreads();

        int jn = j + NSTAGE - 1;
        if (jn < KSTEPS) load_stage(jn, jn % NSTAGE);
        cp_commit();

        const __half* Ac = &As[0][0] + st * 128 * ASTR;
        const __half* Bc = &Bs[0][0] + st * 16 * BSTR;

        wmma::fragment<wmma::matrix_a, 16, 16, 16, __half, wmma::row_major> af[4];
        wmma::fragment<wmma::matrix_b, 16, 16, 16, __half, wmma::row_major> bf[2];
#pragma unroll
        for (int mi = 0; mi < 4; mi++)
            wmma::load_matrix_sync(af[mi], Ac + (wm * 64 + mi * 16) * ASTR, ASTR);
#pragma unroll
        for (int ni = 0; ni < 2; ni++)
            wmma::load_matrix_sync(bf[ni], Bc + wn * 32 + ni * 16, BSTR);
#pragma unroll
        for (int mi = 0; mi < 4; mi++)
#pragma unroll
            for (int ni = 0; ni < 2; ni++)
                wmma::mma_sync(acc[mi][ni], af[mi], bf[ni], acc[mi][ni]);
    }

#pragma unroll
    for (int mi = 0; mi < 4; mi++)
#pragma unroll
        for (int ni = 0; ni < 2; ni++) {
            int r0 = m0 + wm * 64 + mi * 16;
            size_t off = (size_t)(r0 >> 5) * 32768
                       + (size_t)((r0 & 31) + SLOTBASE) * 512
                       + n0 + wn * 32 + ni * 16;
            wmma::store_matrix_sync(out + off, acc[mi][ni], 512, wmma::mem_row_major);
        }
}

// ============================================================
extern "C" void kernel_launch(void* const* d_in, const int* in_sizes, int n_in,
                              void* d_out, int out_size)
{
    const float* fs      = (const float*)d_in[0];
    const float* swin    = (const float*)d_in[1];
    const float* pitch   = (const float*)d_in[2];
    const int*   tlen    = (const int*)  d_in[3];
    const float* conv_w  = (const float*)d_in[4];
    const float* ln_w    = (const float*)d_in[5];
    const float* ln_b    = (const float*)d_in[6];
    const float* dense_w = (const float*)d_in[7];
    const float* dense_b = (const float*)d_in[8];
    const float* proj_w  = (const float*)d_in[9];
    const float* proj_b  = (const float*)d_in[10];
    const float* pitch_w = (const float*)d_in[11];
    const float* pitch_b = (const float*)d_in[12];
    const float* swin_w  = (const float*)d_in[13];
    const float* swin_b  = (const float*)d_in[14];
    float* out = (float*)d_out;

    static cudaStream_t s1 = nullptr;
    static cudaEvent_t ev_root = nullptr, ev_fires = nullptr, ev_end = nullptr;
    static bool init_tried = false;
    if (!init_tried) {
        init_tried = true;
        if (cudaStreamCreateWithFlags(&s1, cudaStreamNonBlocking) != cudaSuccess) s1 = nullptr;
        if (s1) {
            if (cudaEventCreateWithFlags(&ev_root,  cudaEventDisableTiming) != cudaSuccess ||
                cudaEventCreateWithFlags(&ev_fires, cudaEventDisableTiming) != cudaSuccess ||
                cudaEventCreateWithFlags(&ev_end,   cudaEventDisableTiming) != cudaSuccess) {
                s1 = nullptr;
            }
        }
    }

    dim3 grid(NTILES, NROWS / 128);   // (4, 512)

    if (s1) {
        cudaEventRecord(ev_root, 0);
        cudaStreamWaitEvent(s1, ev_root, 0);

        // s1: independent pitch chain
        pack_b_kernel<<<(NTILES * (KS_SW + KS_PI) * 2048 + 255) / 256, 256, 0, s1>>>(
            swin_w, swin_b, pitch_w, pitch_b);
        pack_a_pitch<<<NROWS / 8, 256, 0, s1>>>(pitch);
        gemm_fp16<KS_PI, 3, 0><<<grid, 256, 0, s1>>>(out);

        // s0: main chain
        alpha_kernel<<<750, 256>>>(fs, conv_w, ln_w, ln_b,
                                   dense_w, dense_b, proj_w, proj_b,
                                   out + ALPHA_OFF);
        fires_kernel<<<BB, 1024>>>(out + ALPHA_OFF, tlen);
        cudaEventRecord(ev_fires, 0);
        pack_a_swin<<<NROWS / 8, 256>>>(swin);

        // qty overlapped on s1
        cudaStreamWaitEvent(s1, ev_fires, 0);
        qty_kernel<<<1, 32, 0, s1>>>(out + QTY_OFF);

        gemm_fp16<KS_SW, 4, 32><<<grid, 256>>>(out);

        cudaEventRecord(ev_end, s1);
        cudaStreamWaitEvent(0, ev_end, 0);
    } else {
        alpha_kernel<<<750, 256>>>(fs, conv_w, ln_w, ln_b,
                                   dense_w, dense_b, proj_w, proj_b,
                                   out + ALPHA_OFF);
        fires_kernel<<<BB, 1024>>>(out + ALPHA_OFF, tlen);
        qty_kernel<<<1, 32>>>(out + QTY_OFF);
        pack_b_kernel<<<(NTILES * (KS_SW + KS_PI) * 2048 + 255) / 256, 256>>>(
            swin_w, swin_b, pitch_w, pitch_b);
        pack_a_pitch<<<NROWS / 8, 256>>>(pitch);
        pack_a_swin<<<NROWS / 8, 256>>>(swin);
        gemm_fp16<KS_SW, 4, 32><<<grid, 256>>>(out);
        gemm_fp16<KS_PI, 3, 0><<<grid, 256>>>(out);
    }
}

// round 16
// speedup vs baseline: 1.1331x; 1.0151x over previous
#include <cuda_runtime.h>
#include <cuda_fp16.h>
#include <mma.h>
#include <cstdint>
using namespace nvcuda;

// ---------------- problem constants ----------------
#define BB    16
#define TT    3000
#define CC    32
#define HH    32
#define WW    375
#define DSW   192
#define PP    32
#define DMODEL 512
#define HID   128
#define NF    128

#define ACOUSTIC_SIZE (BB * NF * 64 * DMODEL)
#define ALPHA_OFF     ACOUSTIC_SIZE
#define QTY_OFF       (ALPHA_OFF + BB * TT)

#define NROWS   (BB * NF * 32)     // 65536 GEMM rows
#define KS_SW   13                 // swin k-steps of 16
#define KS_PI   3                  // pitch k-steps
#define NTILES  4                  // DMODEL / 128

// ---------------- scratch ----------------
__device__ int    g_fire_w[BB * NF];
__device__ float  g_qdiff[BB];
__device__ __align__(256) __half g_Asw[(size_t)KS_SW * NROWS * 16];
__device__ __align__(256) __half g_Api[(size_t)KS_PI * NROWS * 16];
__device__ __align__(256) __half g_Bsw[NTILES * KS_SW * 2048];
__device__ __align__(256) __half g_Bpi[NTILES * KS_PI * 2048];

// ---------------- helpers ----------------
__device__ __forceinline__ float warp_sum(float v) {
#pragma unroll
    for (int o = 16; o > 0; o >>= 1) v += __shfl_xor_sync(0xffffffffu, v, o);
    return v;
}
__device__ __forceinline__ void cp16s(unsigned saddr, const void* g) {
    asm volatile("cp.async.cg.shared.global [%0], [%1], 16;" :: "r"(saddr), "l"(g));
}
__device__ __forceinline__ void cp_commit() {
    asm volatile("cp.async.commit_group;" ::: "memory");
}
template <int N>
__device__ __forceinline__ void cp_wait() {
    asm volatile("cp.async.wait_group %0;" :: "n"(N) : "memory");
}

// ============================================================
// Kernel 1: alpha — 8 consecutive t per warp, float4 weight LDS
// ============================================================
__global__ __launch_bounds__(256) void alpha_kernel(
    const float* __restrict__ fs,
    const float* __restrict__ conv_w,
    const float* __restrict__ ln_w,  const float* __restrict__ ln_b,
    const float* __restrict__ dense_w, const float* __restrict__ dense_b,
    const float* __restrict__ proj_w,  const float* __restrict__ proj_b,
    float* __restrict__ alpha_out)
{
    __shared__ float4 s_dw4[CC * 32];
    __shared__ float4 s_db4[32], s_pw4[32];
    __shared__ float  s_cw[CC * 3], s_lnw[CC], s_lnb[CC];

    int tid = threadIdx.x;
    for (int i = tid; i < CC * HID; i += 256) {
        int cc = i >> 7, j = i & 127;
        int q = j >> 5, l = j & 31;
        ((float*)s_dw4)[cc * 128 + l * 4 + q] = dense_w[i];
    }
    if (tid < HID) {
        int q = tid >> 5, l = tid & 31;
        ((float*)s_db4)[l * 4 + q] = dense_b[tid];
        ((float*)s_pw4)[l * 4 + q] = proj_w[tid];
    }
    if (tid < CC * 3) s_cw[tid] = conv_w[tid];
    if (tid < CC) { s_lnw[tid] = ln_w[tid]; s_lnb[tid] = ln_b[tid]; }
    __syncthreads();

    int warp = tid >> 5, lane = tid & 31;
    int g = blockIdx.x * 8 + warp;
    int t0 = (g * 8) % TT;
    int b  = (g * 8) / TT;

    const float* base = fs + ((size_t)b * TT + t0) * CC + lane;
    float xv[10];
#pragma unroll
    for (int j = 0; j < 10; j++) {
        int t = t0 - 1 + j;
        xv[j] = (t >= 0 && t < TT) ? base[(j - 1) * CC] : 0.f;
    }

    float cw0 = s_cw[lane * 3], cw1 = s_cw[lane * 3 + 1], cw2 = s_cw[lane * 3 + 2];
    float lnw = s_lnw[lane], lnb = s_lnb[lane];

    float xn[8];
#pragma unroll
    for (int i = 0; i < 8; i++) {
        float x = fmaf(cw0, xv[i], fmaf(cw1, xv[i + 1], cw2 * xv[i + 2])) + xv[i + 1];
        float mu  = warp_sum(x) * (1.f / CC);
        float d   = x - mu;
        float var = warp_sum(d * d) * (1.f / CC);
        xn[i] = d * rsqrtf(var + 1e-5f) * lnw + lnb;
    }

    float4 db = s_db4[lane];
    float4 h[8] = {db, db, db, db, db, db, db, db};
#pragma unroll
    for (int cc = 0; cc < CC; cc++) {
        float4 w = s_dw4[cc * 32 + lane];
#pragma unroll
        for (int i = 0; i < 8; i++) {
            float v = __shfl_sync(0xffffffffu, xn[i], cc);
            h[i].x = fmaf(v, w.x, h[i].x);
            h[i].y = fmaf(v, w.y, h[i].y);
            h[i].z = fmaf(v, w.z, h[i].z);
            h[i].w = fmaf(v, w.w, h[i].w);
        }
    }

    float4 pw = s_pw4[lane];
    float ps[8];
#pragma unroll
    for (int i = 0; i < 8; i++) {
        float p = fmaxf(h[i].x, 0.f) * pw.x + fmaxf(h[i].y, 0.f) * pw.y
                + fmaxf(h[i].z, 0.f) * pw.z + fmaxf(h[i].w, 0.f) * pw.w;
        ps[i] = warp_sum(p);
    }

    if (lane < 8) {
        float psel = ps[0];
#pragma unroll
        for (int i = 1; i < 8; i++) if (lane == i) psel = ps[i];
        float a  = psel + proj_b[0];
        float sp = fmaxf(a, 0.f) + log1pf(expf(-fabsf(a)));
        alpha_out[(size_t)b * TT + t0 + lane] = sp;
    }
}

// ============================================================
// Kernel 2: fires (warp-scan, 2 barriers)
// ============================================================
__global__ __launch_bounds__(1024) void fires_kernel(
    const float* __restrict__ alpha, const int* __restrict__ tlen)
{
    __shared__ int   s_wsum[32];
    __shared__ int   s_frame[NF];
    __shared__ float s_red[32];

    int b = blockIdx.x, tid = threadIdx.x;
    int lane = tid & 31, warp = tid >> 5;
    if (tid < NF) s_frame[tid] = TT - 1;

    const float* arow = alpha + (size_t)b * TT;
    int base = tid * 3;
    int pred[3] = {0, 0, 0};
    int mycnt = 0; float onset = 0.f;
#pragma unroll
    for (int i = 0; i < 3; i++) {
        int t = base + i;
        if (t < TT) {
            float a = arow[t];
            int pr = (a > 1.0f);
            pred[i] = pr; mycnt += pr;
            onset += 1.f / (1.f + expf(-(a - 1.0f) * 10.f));
        }
    }
    int scan = mycnt;
#pragma unroll
    for (int o = 1; o < 32; o <<= 1) {
        int v = __shfl_up_sync(0xffffffffu, scan, o);
        if (lane >= o) scan += v;
    }
    if (lane == 31) s_wsum[warp] = scan;
    float os = warp_sum(onset);
    if (lane == 0) s_red[warp] = os;
    __syncthreads();
    if (warp == 0) {
        int ws = s_wsum[lane];
#pragma unroll
        for (int o = 1; o < 32; o <<= 1) {
            int v = __shfl_up_sync(0xffffffffu, ws, o);
            if (lane >= o) ws += v;
        }
        s_wsum[lane] = ws;
        float v = warp_sum(s_red[lane]);
        if (lane == 0) g_qdiff[b] = fabsf(v - (float)tlen[b]);
    }
    __syncthreads();
    int c = scan - mycnt + (warp > 0 ? s_wsum[warp - 1] : 0);
#pragma unroll
    for (int i = 0; i < 3; i++) {
        if (pred[i]) {
            c += 1;
            if (c <= NF) s_frame[c - 1] = base + i;
        }
    }
    __syncthreads();
    if (tid < NF) g_fire_w[b * NF + tid] = s_frame[tid] >> 3;
}

__global__ void qty_kernel(float* __restrict__ out) {
    int tid = threadIdx.x;
    float v = (tid < BB) ? g_qdiff[tid] : 0.f;
    v = warp_sum(v);
    if (tid == 0) out[0] = v * (1.f / BB);
}

// ============================================================
// Packing kernels (fp16 RN, bias row folded, k-step blocked)
// ============================================================
__global__ __launch_bounds__(256) void pack_b_kernel(
    const float* __restrict__ sw_w, const float* __restrict__ sw_b,
    const float* __restrict__ pi_w, const float* __restrict__ pi_b)
{
    int idx = blockIdx.x * 256 + threadIdx.x;
    const int SWTOT = NTILES * KS_SW * 2048;
    if (idx < SWTOT) {
        int nt = idx / (KS_SW * 2048);
        int rem = idx % (KS_SW * 2048);
        int j = rem / 2048, e = rem % 2048;
        int kr = e >> 7, n = e & 127;
        int k = j * 16 + kr;
        float v = (k < DSW) ? sw_w[k * DMODEL + nt * 128 + n]
                : (k == DSW ? sw_b[nt * 128 + n] : 0.f);
        g_Bsw[idx] = __float2half_rn(v);
    } else {
        int x = idx - SWTOT;
        if (x >= NTILES * KS_PI * 2048) return;
        int nt = x / (KS_PI * 2048);
        int rem = x % (KS_PI * 2048);
        int j = rem / 2048, e = rem % 2048;
        int kr = e >> 7, n = e & 127;
        int k = j * 16 + kr;
        float v = (k < 32) ? pi_w[k * DMODEL + nt * 128 + n]
                : (k == 32 ? pi_b[nt * 128 + n] : 0.f);
        g_Bpi[x] = __float2half_rn(v);
    }
}

__global__ __launch_bounds__(256) void pack_a_pitch(const float* __restrict__ pitch)
{
    int warp = threadIdx.x >> 5, lane = threadIdx.x & 31;
    int r = blockIdx.x * 8 + warp;
    float v = pitch[(size_t)r * 32 + lane];
    g_Api[((size_t)(lane >> 4) * NROWS + r) * 16 + (lane & 15)] = __float2half_rn(v);
    if (lane < 16)
        g_Api[((size_t)2 * NROWS + r) * 16 + lane] =
            __float2half_rn(lane == 0 ? 1.f : 0.f);
}

__global__ __launch_bounds__(256) void pack_a_swin(const float* __restrict__ swin)
{
    int warp = threadIdx.x >> 5, lane = threadIdx.x & 31;
    int r = blockIdx.x * 8 + warp;
    int b = r >> 12, n = (r >> 5) & 127, h = r & 31;
    int w = g_fire_w[b * NF + n];
    const float* src = swin + (size_t)((b * HH + h) * WW + w) * DSW;
#pragma unroll
    for (int j = 0; j < 6; j++) {
        int k = j * 32 + lane;
        float v = src[k];
        g_Asw[((size_t)(k >> 4) * NROWS + r) * 16 + (k & 15)] = __float2half_rn(v);
    }
    if (lane < 16)
        g_Asw[((size_t)12 * NROWS + r) * 16 + lane] =
            __float2half_rn(lane == 0 ? 1.f : 0.f);
}

// ============================================================
// fp16 wmma GEMM: 128x128 tile, k-step(16) multistage cp.async
// (proven R10 schedule: static smem, rolled loop)
// ============================================================
#define ASTR 24     // halves (48B rows)
#define BSTR 136    // halves (272B rows)

template<int KSTEPS, int NSTAGE, int SLOTBASE>
__global__ __launch_bounds__(256, 2) void gemm_fp16(float* __restrict__ out)
{
    __shared__ __align__(16) __half As[NSTAGE][128 * ASTR];
    __shared__ __align__(16) __half Bs[NSTAGE][16 * BSTR];

    const __half* __restrict__ Apk = (SLOTBASE == 0) ? g_Api : g_Asw;
    const __half* __restrict__ Bpk = (SLOTBASE == 0) ? g_Bpi : g_Bsw;

    int tid = threadIdx.x;
    int m0 = blockIdx.y * 128;
    int nt = blockIdx.x;
    int n0 = nt * 128;

    unsigned sA = (unsigned)__cvta_generic_to_shared(&As[0][0]);
    unsigned sB = (unsigned)__cvta_generic_to_shared(&Bs[0][0]);
    const unsigned ASTAGE = 128 * ASTR * sizeof(__half);
    const unsigned BSTAGE = 16 * BSTR * sizeof(__half);

    int arow = tid >> 1, aseg = tid & 1;
    int brow = tid >> 4, bseg = tid & 15;

    auto load_stage = [&](int j, int st) {
        const __half* asrc = Apk + ((size_t)j * NROWS + m0) * 16;
        const __half* bsrc = Bpk + (size_t)(nt * KSTEPS + j) * 2048;
        cp16s(sA + st * ASTAGE + arow * (ASTR * 2) + aseg * 16,
              asrc + arow * 16 + aseg * 8);
        cp16s(sB + st * BSTAGE + brow * (BSTR * 2) + bseg * 16,
              bsrc + brow * 128 + bseg * 8);
    };

    int warp = tid >> 5;
    int wm = warp & 1, wn = warp >> 1;

    wmma::fragment<wmma::accumulator, 16, 16, 16, float> acc[4][2];
#pragma unroll
    for (int mi = 0; mi < 4; mi++)
#pragma unroll
        for (int ni = 0; ni < 2; ni++) wmma::fill_fragment(acc[mi][ni], 0.f);

#pragma unroll
    for (int p = 0; p < NSTAGE - 1; p++) { load_stage(p, p); cp_commit(); }

    for (int j = 0; j < KSTEPS; j++) {
        int st = j % NSTAGE;
        cp_wait<NSTAGE - 2>();
        __syncthreads();

        int jn = j + NSTAGE - 1;
        if (jn < KSTEPS) load_stage(jn, jn % NSTAGE);
        cp_commit();

        const __half* Ac = &As[0][0] + st * 128 * ASTR;
        const __half* Bc = &Bs[0][0] + st * 16 * BSTR;

        wmma::fragment<wmma::matrix_a, 16, 16, 16, __half, wmma::row_major> af[4];
        wmma::fragment<wmma::matrix_b, 16, 16, 16, __half, wmma::row_major> bf[2];
#pragma unroll
        for (int mi = 0; mi < 4; mi++)
            wmma::load_matrix_sync(af[mi], Ac + (wm * 64 + mi * 16) * ASTR, ASTR);
#pragma unroll
        for (int ni = 0; ni < 2; ni++)
            wmma::load_matrix_sync(bf[ni], Bc + wn * 32 + ni * 16, BSTR);
#pragma unroll
        for (int mi = 0; mi < 4; mi++)
#pragma unroll
            for (int ni = 0; ni < 2; ni++)
                wmma::mma_sync(acc[mi][ni], af[mi], bf[ni], acc[mi][ni]);
    }

#pragma unroll
    for (int mi = 0; mi < 4; mi++)
#pragma unroll
        for (int ni = 0; ni < 2; ni++) {
            int r0 = m0 + wm * 64 + mi * 16;
            size_t off = (size_t)(r0 >> 5) * 32768
                       + (size_t)((r0 & 31) + SLOTBASE) * 512
                       + n0 + wn * 32 + ni * 16;
            wmma::store_matrix_sync(out + off, acc[mi][ni], 512, wmma::mem_row_major);
        }
}

// ============================================================
extern "C" void kernel_launch(void* const* d_in, const int* in_sizes, int n_in,
                              void* d_out, int out_size)
{
    const float* fs      = (const float*)d_in[0];
    const float* swin    = (const float*)d_in[1];
    const float* pitch   = (const float*)d_in[2];
    const int*   tlen    = (const int*)  d_in[3];
    const float* conv_w  = (const float*)d_in[4];
    const float* ln_w    = (const float*)d_in[5];
    const float* ln_b    = (const float*)d_in[6];
    const float* dense_w = (const float*)d_in[7];
    const float* dense_b = (const float*)d_in[8];
    const float* proj_w  = (const float*)d_in[9];
    const float* proj_b  = (const float*)d_in[10];
    const float* pitch_w = (const float*)d_in[11];
    const float* pitch_b = (const float*)d_in[12];
    const float* swin_w  = (const float*)d_in[13];
    const float* swin_b  = (const float*)d_in[14];
    float* out = (float*)d_out;

    static cudaStream_t s1 = nullptr;
    static cudaEvent_t ev_root = nullptr, ev_fires = nullptr, ev_end = nullptr;
    static bool init_tried = false;
    if (!init_tried) {
        init_tried = true;
        if (cudaStreamCreateWithFlags(&s1, cudaStreamNonBlocking) != cudaSuccess) s1 = nullptr;
        if (s1) {
            if (cudaEventCreateWithFlags(&ev_root,  cudaEventDisableTiming) != cudaSuccess ||
                cudaEventCreateWithFlags(&ev_fires, cudaEventDisableTiming) != cudaSuccess ||
                cudaEventCreateWithFlags(&ev_end,   cudaEventDisableTiming) != cudaSuccess) {
                s1 = nullptr;
            }
        }
    }

    dim3 grid(NTILES, NROWS / 128);   // (4, 512)

    if (s1) {
        cudaEventRecord(ev_root, 0);
        cudaStreamWaitEvent(s1, ev_root, 0);

        // s1: independent pitch chain
        pack_b_kernel<<<(NTILES * (KS_SW + KS_PI) * 2048 + 255) / 256, 256, 0, s1>>>(
            swin_w, swin_b, pitch_w, pitch_b);
        pack_a_pitch<<<NROWS / 8, 256, 0, s1>>>(pitch);
        gemm_fp16<KS_PI, 3, 0><<<grid, 256, 0, s1>>>(out);

        // s0: main chain
        alpha_kernel<<<750, 256>>>(fs, conv_w, ln_w, ln_b,
                                   dense_w, dense_b, proj_w, proj_b,
                                   out + ALPHA_OFF);
        fires_kernel<<<BB, 1024>>>(out + ALPHA_OFF, tlen);
        cudaEventRecord(ev_fires, 0);
        pack_a_swin<<<NROWS / 8, 256>>>(swin);

        // qty overlapped on s1 (needs only fires' g_qdiff)
        cudaStreamWaitEvent(s1, ev_fires, 0);
        qty_kernel<<<1, 32, 0, s1>>>(out + QTY_OFF);

        gemm_fp16<KS_SW, 4, 32><<<grid, 256>>>(out);

        cudaEventRecord(ev_end, s1);
        cudaStreamWaitEvent(0, ev_end, 0);
    } else {
        alpha_kernel<<<750, 256>>>(fs, conv_w, ln_w, ln_b,
                                   dense_w, dense_b, proj_w, proj_b,
                                   out + ALPHA_OFF);
        fires_kernel<<<BB, 1024>>>(out + ALPHA_OFF, tlen);
        qty_kernel<<<1, 32>>>(out + QTY_OFF);
        pack_b_kernel<<<(NTILES * (KS_SW + KS_PI) * 2048 + 255) / 256, 256>>>(
            swin_w, swin_b, pitch_w, pitch_b);
        pack_a_pitch<<<NROWS / 8, 256>>>(pitch);
        pack_a_swin<<<NROWS / 8, 256>>>(swin);
        gemm_fp16<KS_SW, 4, 32><<<grid, 256>>>(out);
        gemm_fp16<KS_PI, 3, 0><<<grid, 256>>>(out);
    }
}